// round 17
// baseline (speedup 1.0000x reference)
#include <cuda_runtime.h>
#include <cuda_bf16.h>
#include <cuda_fp16.h>
#include <math.h>
#include <stdint.h>

#define BB 128
#define PP 196
#define EE 2048
#define HH 512
#define VV 10000
#define VPAD 10112
#define TT 20
#define SS 19
#define XK 3072
#define G4 2048
#define QG 2560
#define HC 1024
// X layout: [emb(0..512) | h(512..1024) | ctx(1024..3072)]
#define XE 0
#define XH 512
#define XC 1024

typedef __nv_bfloat16 bf16;

// ---------------- device global scratch ----------------
__device__ bf16   g_imgh[(size_t)BB * PP * EE];
__device__ bf16   g_imgl[(size_t)BB * PP * EE];
__device__ __half g_img16[(size_t)BB * PP * EE];
__device__ __half g_Ws16[(size_t)BB * PP * HH];
__device__ bf16   g_BWatt_h[HH * EE],  g_BWatt_l[HH * EE];
__device__ bf16   g_BWihc_h[HC * EE],  g_BWihc_l[HC * EE];
__device__ bf16   g_Bqg_h[QG * HH],    g_Bqg_l[QG * HH];
__device__ bf16   g_BWcat_h[(size_t)G4 * XK], g_BWcat_l[(size_t)G4 * XK]; // K=[emb|h|ctx]
__device__ bf16   g_BWdo_h[(size_t)VPAD * HH], g_BWdo_l[(size_t)VPAD * HH];
__device__ bf16   g_avgh[BB * EE], g_avgl[BB * EE];
__device__ bf16   g_Xh[BB * XK],   g_Xl[BB * XK];
__device__ bf16   g_Hh[(size_t)SS * BB * HH], g_Hl[(size_t)SS * BB * HH];
__device__ float  g_c[BB * HH];
__device__ float  g_alpha[BB * PP];
__device__ float  g_qgp[4 * BB * QG];
__device__ float  g_gatesp[8 * BB * G4];   // 0..3: gatesB ; 4..5 / 6..7: gatesA by parity

// ---------------- helpers ----------------
__device__ __forceinline__ uint32_t s2u(const void* p) {
    uint32_t a;
    asm("{ .reg .u64 t; cvta.to.shared.u64 t, %1; cvt.u32.u64 %0, t; }" : "=r"(a) : "l"(p));
    return a;
}
__device__ __forceinline__ void cp16(uint32_t s, const void* g) {
    asm volatile("cp.async.cg.shared.global [%0], [%1], 16;" :: "r"(s), "l"(g) : "memory");
}
__device__ __forceinline__ void cp_commit() { asm volatile("cp.async.commit_group;" ::: "memory"); }
template <int N> __device__ __forceinline__ void cp_wait() {
    asm volatile("cp.async.wait_group %0;" :: "n"(N) : "memory");
}
__device__ __forceinline__ void ldsm4(uint32_t* r, uint32_t addr) {
    asm volatile("ldmatrix.sync.aligned.m8n8.x4.shared.b16 {%0,%1,%2,%3}, [%4];"
                 : "=r"(r[0]), "=r"(r[1]), "=r"(r[2]), "=r"(r[3]) : "r"(addr));
}
__device__ __forceinline__ void ldsm2t(uint32_t* r, uint32_t addr) {
    asm volatile("ldmatrix.sync.aligned.m8n8.x2.trans.shared.b16 {%0,%1}, [%2];"
                 : "=r"(r[0]), "=r"(r[1]) : "r"(addr));
}
__device__ __forceinline__ void mma16816(float* d, const uint32_t* a, const uint32_t* b) {
    asm volatile("mma.sync.aligned.m16n8k16.row.col.f32.bf16.bf16.f32 "
                 "{%0,%1,%2,%3}, {%4,%5,%6,%7}, {%8,%9}, {%0,%1,%2,%3};"
                 : "+f"(d[0]), "+f"(d[1]), "+f"(d[2]), "+f"(d[3])
                 : "r"(a[0]), "r"(a[1]), "r"(a[2]), "r"(a[3]), "r"(b[0]), "r"(b[1]));
}
__device__ __forceinline__ void mma16816h(float* d, const uint32_t* a, const uint32_t* b) {
    asm volatile("mma.sync.aligned.m16n8k16.row.col.f32.f16.f16.f32 "
                 "{%0,%1,%2,%3}, {%4,%5,%6,%7}, {%8,%9}, {%0,%1,%2,%3};"
                 : "+f"(d[0]), "+f"(d[1]), "+f"(d[2]), "+f"(d[3])
                 : "r"(a[0]), "r"(a[1]), "r"(a[2]), "r"(a[3]), "r"(b[0]), "r"(b[1]));
}
__device__ __forceinline__ float tanh_hw(float x) {
    float r;
    asm("tanh.approx.f32 %0, %1;" : "=f"(r) : "f"(x));
    return r;
}
__device__ __forceinline__ void split2(float v, bf16* ph, bf16* pl) {
    bf16 h = __float2bfloat16(v);
    *ph = h;
    *pl = __float2bfloat16(v - __bfloat162float(h));
}
__device__ __forceinline__ uint32_t pack_h2(__half a, __half b) {
    __half2 h2 = __halves2half2(a, b);
    uint32_t u;
    *(__half2*)&u = h2;
    return u;
}
__device__ __forceinline__ void store_out(float* p, float v) { *p = v; }
__device__ __forceinline__ void store_out(__half* p, float v) { *p = __float2half(v); }

// ---------------- split-bf16 HMMA GEMM, 4-stage pipeline, split-K via grid.z ----
// A/B pointers point at the START of the K-range; lda/ldb are full row strides.
#define TILE_B   10240
#define BUF_B    40960
#define SMEM_SZ  163840

template <typename OT>
__global__ void __launch_bounds__(256, 1)
tc_gemm(const bf16* __restrict__ Ah, const bf16* __restrict__ Al, int lda,
        const bf16* __restrict__ Bh, const bf16* __restrict__ Bl, int ldb,
        const float* __restrict__ bias, OT* __restrict__ C, int ldc,
        long tile_stride, int Nstore, int K)
{
    extern __shared__ char sm[];
    const int tid = threadIdx.x, lane = tid & 31, wid = tid >> 5;
    const int m0 = blockIdx.y << 7, n0 = blockIdx.x << 7;
    const int wy = wid & 1, wx = wid >> 1;
    const uint32_t sb = s2u(sm);

    const int kc = K / gridDim.z;
    const size_t kofs = (size_t)blockIdx.z * kc * 2;
    C += (size_t)blockIdx.z * gridDim.y * tile_stride + (size_t)blockIdx.y * tile_stride;

    const char* gAh = (const char*)(Ah + (size_t)m0 * lda) + kofs;
    const char* gAl = (const char*)(Al + (size_t)m0 * lda) + kofs;
    const char* gBh = (const char*)(Bh + (size_t)n0 * ldb) + kofs;
    const char* gBl = (const char*)(Bl + (size_t)n0 * ldb) + kofs;
    const size_t strA = (size_t)lda * 2, strB = (size_t)ldb * 2;

    const int arow = lane & 15;
    const int acol = (lane >> 4) << 4;
    const int brow = ((lane >> 4) << 3) + (lane & 7);
    const int bcol = ((lane >> 3) & 1) << 4;
    const uint32_t aoff = (uint32_t)((wy * 64 + arow) * 80 + acol);
    const uint32_t boff = (uint32_t)((wx * 32 + brow) * 80 + bcol);

    float acc[4][4][4] = {};
    const int nk = kc >> 5;

    auto issue = [&](int ch) {
        if (ch < nk) {
            const int k0b = ch << 6;
            const uint32_t s0 = sb + (ch & 3) * BUF_B;
            #pragma unroll
            for (int half = 0; half < 2; half++) {
                int u  = tid + half * 256;
                int r  = u >> 2;
                int sg = (u & 3) << 4;
                uint32_t s = s0 + r * 80 + sg;
                size_t gA = (size_t)r * strA + k0b + sg;
                size_t gB = (size_t)r * strB + k0b + sg;
                cp16(s,              gAh + gA);
                cp16(s + TILE_B,     gAl + gA);
                cp16(s + 2 * TILE_B, gBh + gB);
                cp16(s + 3 * TILE_B, gBl + gB);
            }
        }
        cp_commit();
    };

    issue(0); issue(1); issue(2);

    for (int ch = 0; ch < nk; ch++) {
        cp_wait<2>();
        __syncthreads();
        issue(ch + 3);

        const uint32_t base = sb + (ch & 3) * BUF_B;
        #pragma unroll
        for (int ks = 0; ks < 2; ks++) {
            uint32_t ah[4][4], al[4][4];
            #pragma unroll
            for (int mi = 0; mi < 4; mi++) {
                uint32_t o = aoff + mi * (16 * 80) + ks * 32;
                ldsm4(ah[mi], base + o);
                ldsm4(al[mi], base + TILE_B + o);
            }
            uint32_t bh[2][4], bl[2][4];
            #pragma unroll
            for (int nj = 0; nj < 2; nj++) {
                uint32_t o = boff + nj * (16 * 80) + ks * 32;
                ldsm4(bh[nj], base + 2 * TILE_B + o);
                ldsm4(bl[nj], base + 3 * TILE_B + o);
            }
            #pragma unroll
            for (int mi = 0; mi < 4; mi++) {
                #pragma unroll
                for (int n8 = 0; n8 < 4; n8++) {
                    const uint32_t* pbh = &bh[n8 >> 1][(n8 & 1) << 1];
                    const uint32_t* pbl = &bl[n8 >> 1][(n8 & 1) << 1];
                    mma16816(acc[mi][n8], ah[mi], pbh);
                    mma16816(acc[mi][n8], ah[mi], pbl);
                    mma16816(acc[mi][n8], al[mi], pbh);
                }
            }
        }
    }

    #pragma unroll
    for (int mi = 0; mi < 4; mi++) {
        #pragma unroll
        for (int n8 = 0; n8 < 4; n8++) {
            int rb = wy * 64 + mi * 16 + (lane >> 2);
            int nb = n0 + wx * 32 + n8 * 8 + ((lane & 3) << 1);
            #pragma unroll
            for (int g = 0; g < 2; g++) {
                int r = rb + g * 8;
                #pragma unroll
                for (int j = 0; j < 2; j++) {
                    int n = nb + j;
                    if (n < Nstore) {
                        float v = acc[mi][n8][g * 2 + j];
                        if (bias) v += bias[n];
                        store_out(C + (size_t)r * ldc + n, v);
                    }
                }
            }
        }
    }
}

// ---------------- conversion kernels ----------------
__global__ void imgprep_kernel(const float* __restrict__ img,
                               bf16* __restrict__ imgh, bf16* __restrict__ imgl,
                               __half* __restrict__ img16,
                               bf16* __restrict__ ah, bf16* __restrict__ al)
{
    int b = blockIdx.y;
    int e = blockIdx.x * 256 + threadIdx.x;
    const size_t base = (size_t)b * PP * EE + e;
    const float* ib = img + base;
    float s = 0;
    #pragma unroll 4
    for (int p = 0; p < PP; p++) {
        float v = ib[(size_t)p * EE];
        s += v;
        size_t o = base + (size_t)p * EE;
        split2(v, imgh + o, imgl + o);
        img16[o] = __float2half(v);
    }
    split2(s * (1.0f / PP), ah + b * EE + e, al + b * EE + e);
}

__global__ void tsplit_kernel(const float* __restrict__ src, bf16* __restrict__ dh,
                              bf16* __restrict__ dl, int Ksrc, int N, int dst_ld, int koff)
{
    __shared__ float t[32][33];
    const int n0 = blockIdx.x << 5, k0 = blockIdx.y << 5;
    #pragma unroll
    for (int j = 0; j < 4; j++) {
        int kk = k0 + threadIdx.y + (j << 3);
        int n  = n0 + threadIdx.x;
        t[threadIdx.y + (j << 3)][threadIdx.x] = (n < N) ? src[(size_t)kk * N + n] : 0.0f;
    }
    __syncthreads();
    #pragma unroll
    for (int j = 0; j < 4; j++) {
        int nn = n0 + threadIdx.y + (j << 3);
        int k  = k0 + threadIdx.x;
        size_t o = (size_t)nn * dst_ld + koff + k;
        split2(t[threadIdx.x][threadIdx.y + (j << 3)], dh + o, dl + o);
    }
}

// ---------------- pointwise kernels ----------------
__global__ void combine_init(const float* __restrict__ hcp,
                             const float* __restrict__ bih, const float* __restrict__ bic,
                             const float* __restrict__ Wemb, const int* __restrict__ cap,
                             float* __restrict__ c, bf16* __restrict__ Xh, bf16* __restrict__ Xl)
{
    int i = blockIdx.x * 256 + threadIdx.x;
    int b = i >> 9, h = i & 511;
    float sh = bih[h], sc = bic[h];
    #pragma unroll
    for (int z = 0; z < 8; z++) {
        sh += hcp[(size_t)z * BB * HC + b * HC + h];
        sc += hcp[(size_t)z * BB * HC + b * HC + HH + h];
    }
    c[i] = tanhf(sc);
    size_t o = (size_t)b * XK + XH + h;
    split2(tanhf(sh), Xh + o, Xl + o);
    int cw = cap[b * TT + 0];
    size_t oe = (size_t)b * XK + XE + h;
    split2(Wemb[(size_t)cw * HH + h], Xh + oe, Xl + oe);
}

// ---------------- attention (scores + softmax), fp16 W_s ----------------
__global__ void __launch_bounds__(1024)
attention_kernel(const __half* __restrict__ Ws, const float* __restrict__ qgp,
                 const float* __restrict__ bU,
                 const float* __restrict__ v_att, const float* __restrict__ bv,
                 float* __restrict__ alpha, float* __restrict__ alpha_out)
{
    __shared__ float qs[HH], vs[HH], es[PP], red[32];
    const int b = blockIdx.x, tid = threadIdx.x;
    const int lane = tid & 31, warp = tid >> 5;
    const size_t qb = (size_t)b * QG;

    for (int i = tid; i < HH; i += 1024) {
        float s = bU[i];
        #pragma unroll
        for (int z = 0; z < 4; z++) s += qgp[(size_t)z * BB * QG + qb + i];
        qs[i] = s;
        vs[i] = v_att[i];
    }
    __syncthreads();

    const __half* Wb = Ws + (size_t)b * PP * HH;
    const float bv0 = bv[0];
    for (int p = warp; p < PP; p += 32) {
        const __half* row = Wb + (size_t)p * HH;
        float s = 0.0f;
        #pragma unroll
        for (int i = 0; i < 8; i++) {
            int h = (lane << 1) + (i << 6);
            float2 f = __half22float2(*(const __half2*)(row + h));
            s += vs[h]     * tanh_hw(f.x + qs[h]);
            s += vs[h + 1] * tanh_hw(f.y + qs[h + 1]);
        }
        #pragma unroll
        for (int o = 16; o; o >>= 1) s += __shfl_xor_sync(0xffffffffu, s, o);
        if (lane == 0) es[p] = s + bv0;
    }
    __syncthreads();

    float m = -1e30f;
    for (int p = tid; p < PP; p += 1024) m = fmaxf(m, es[p]);
    #pragma unroll
    for (int o = 16; o; o >>= 1) m = fmaxf(m, __shfl_xor_sync(0xffffffffu, m, o));
    if (lane == 0) red[warp] = m;
    __syncthreads();
    if (warp == 0) {
        float t = red[lane];
        #pragma unroll
        for (int o = 16; o; o >>= 1) t = fmaxf(t, __shfl_xor_sync(0xffffffffu, t, o));
        if (lane == 0) red[0] = t;
    }
    __syncthreads();
    m = red[0];
    __syncthreads();
    float sum = 0.0f;
    for (int p = tid; p < PP; p += 1024) { float ev = expf(es[p] - m); es[p] = ev; sum += ev; }
    #pragma unroll
    for (int o = 16; o; o >>= 1) sum += __shfl_xor_sync(0xffffffffu, sum, o);
    if (lane == 0) red[warp] = sum;
    __syncthreads();
    if (warp == 0) {
        float t = red[lane];
        #pragma unroll
        for (int o = 16; o; o >>= 1) t += __shfl_xor_sync(0xffffffffu, t, o);
        if (lane == 0) red[0] = t;
    }
    __syncthreads();
    float inv = 1.0f / red[0];
    for (int p = tid; p < PP; p += 1024) {
        float a = es[p] * inv;
        alpha[b * PP + p] = a;
        alpha_out[(size_t)b * (SS * PP) + p] = a;
    }
}

// ---------------- context as fp16 HMMA ----------------
__global__ void __launch_bounds__(256)
ctx_mma_kernel(const __half* __restrict__ img16, const float* __restrict__ alpha,
               const float* __restrict__ qgp, const float* __restrict__ bfb,
               bf16* __restrict__ Xh, bf16* __restrict__ Xl)
{
    __shared__ __half tile[2][16][512];
    __shared__ float  al_s[208];
    const int b = blockIdx.y;
    const int n_cta = blockIdx.x << 9;
    const int tid = threadIdx.x, lane = tid & 31, warp = tid >> 5;

    for (int i = tid; i < 208; i += 256) al_s[i] = (i < PP) ? alpha[b * PP + i] : 0.0f;

    const __half* gimg = img16 + (size_t)b * PP * EE + n_cta;
    const uint32_t tb = s2u(&tile[0][0][0]);

    auto issue = [&](int ck, int buf) {
        #pragma unroll
        for (int i = 0; i < 4; i++) {
            int idx = tid + (i << 8);
            int r = idx >> 6, sg = (idx & 63) << 3;
            int p = (ck << 4) + r;
            if (p < PP)
                cp16(tb + (buf * 16 + r) * 1024 + sg * 2,
                     gimg + (size_t)p * EE + sg);
        }
        cp_commit();
    };

    const int NC = 13;
    issue(0, 0);

    float acc[8][4] = {};
    const int t4 = lane & 3;

    for (int ck = 0; ck < NC; ck++) {
        if (ck + 1 < NC) { issue(ck + 1, (ck + 1) & 1); cp_wait<1>(); }
        else             { cp_wait<0>(); }
        __syncthreads();

        uint32_t a_h[4] = {0, 0, 0, 0}, a_l[4] = {0, 0, 0, 0};
        if (lane < 4) {
            int k0 = (ck << 4) + (t4 << 1);
            float x0 = al_s[k0], x1 = al_s[k0 + 1];
            float x2 = al_s[k0 + 8], x3 = al_s[k0 + 9];
            __half h0 = __float2half(x0), h1 = __float2half(x1);
            __half h2 = __float2half(x2), h3 = __float2half(x3);
            a_h[0] = pack_h2(h0, h1);
            a_h[2] = pack_h2(h2, h3);
            a_l[0] = pack_h2(__float2half(x0 - __half2float(h0)),
                             __float2half(x1 - __half2float(h1)));
            a_l[2] = pack_h2(__float2half(x2 - __half2float(h2)),
                             __float2half(x3 - __half2float(h3)));
        }

        const uint32_t rowaddr = tb + ((ck & 1) * 16 + (lane & 15)) * 1024 + (warp << 7);
        #pragma unroll
        for (int f = 0; f < 8; f++) {
            uint32_t brg[2];
            ldsm2t(brg, rowaddr + (f << 4));
            mma16816h(acc[f], a_h, brg);
            mma16816h(acc[f], a_l, brg);
        }
        __syncthreads();
    }

    float* gate_s = (float*)&tile[0][0][0];
    #pragma unroll
    for (int i = 0; i < 2; i++) {
        int el = tid + (i << 8);
        int e = n_cta + el;
        float gs = bfb[e];
        #pragma unroll
        for (int z = 0; z < 4; z++) gs += qgp[(size_t)z * BB * QG + (size_t)b * QG + HH + e];
        gate_s[el] = 1.0f / (1.0f + expf(-gs));
    }
    __syncthreads();

    if (lane < 4) {
        #pragma unroll
        for (int f = 0; f < 8; f++) {
            #pragma unroll
            for (int j = 0; j < 2; j++) {
                int el = (warp << 6) + (f << 3) + (t4 << 1) + j;
                int e = n_cta + el;
                float v = acc[f][j] * gate_s[el];
                size_t o = (size_t)b * XK + XC + e;
                split2(v, Xh + o, Xl + o);
            }
        }
    }
}

// LSTM: sum gatesB slices 0..3 + gatesA slices zA..zA+1
__global__ void lstm_kernel(const float* __restrict__ gatesp, int zA,
                            const float* __restrict__ bl,
                            float* __restrict__ c, bf16* __restrict__ Xh, bf16* __restrict__ Xl,
                            bf16* __restrict__ Hh, bf16* __restrict__ Hl,
                            const float* __restrict__ Wemb, const int* __restrict__ cap, int t)
{
    int i = blockIdx.x * 256 + threadIdx.x;
    int b = i >> 9, h = i & 511;
    float g[4];
    #pragma unroll
    for (int k = 0; k < 4; k++) {
        int j = k * HH + h;
        float s = bl[j];
        #pragma unroll
        for (int z = 0; z < 4; z++) s += gatesp[(size_t)z * BB * G4 + b * G4 + j];
        s += gatesp[(size_t)zA * BB * G4 + b * G4 + j];
        s += gatesp[(size_t)(zA + 1) * BB * G4 + b * G4 + j];
        g[k] = s;
    }
    float ig = 1.0f / (1.0f + expf(-g[0]));
    float fg = 1.0f / (1.0f + expf(-g[1]));
    float gg = tanhf(g[2]);
    float og = 1.0f / (1.0f + expf(-g[3]));
    float cn = fg * c[i] + ig * gg;
    c[i] = cn;
    float hn = og * tanhf(cn);
    size_t o = (size_t)b * XK + XH + h;
    split2(hn, Xh + o, Xl + o);
    size_t oh = (size_t)(t * BB + b) * HH + h;
    split2(hn, Hh + oh, Hl + oh);
    int cw = cap[b * TT + (t + 1)];
    size_t oe = (size_t)b * XK + XE + h;
    split2(Wemb[(size_t)cw * HH + h], Xh + oe, Xl + oe);
}

// ---------------- host launch ----------------
extern "C" void kernel_launch(void* const* d_in, const int* in_sizes, int n_in,
                              void* d_out, int out_size)
{
    const float* img   = (const float*)d_in[0];
    const int*   cap   = (const int*)  d_in[1];
    const float* U_att = (const float*)d_in[2];
    const float* bU    = (const float*)d_in[3];
    const float* W_att = (const float*)d_in[4];
    const float* bW    = (const float*)d_in[5];
    const float* v_att = (const float*)d_in[6];
    const float* bv    = (const float*)d_in[7];
    const float* Wih   = (const float*)d_in[8];
    const float* bih   = (const float*)d_in[9];
    const float* Wic   = (const float*)d_in[10];
    const float* bic   = (const float*)d_in[11];
    const float* Wfb   = (const float*)d_in[12];
    const float* bfb   = (const float*)d_in[13];
    const float* Wdo   = (const float*)d_in[14];
    const float* bdo   = (const float*)d_in[15];
    const float* Wemb  = (const float*)d_in[16];
    const float* Wl    = (const float*)d_in[17];
    const float* Ul    = (const float*)d_in[18];
    const float* bl    = (const float*)d_in[19];

    float* preds  = (float*)d_out;
    float* alphas = (float*)d_out + (size_t)BB * SS * VV;

    bf16 *imgh, *imgl, *BWatt_h, *BWatt_l, *BWihc_h, *BWihc_l;
    bf16 *Bqg_h, *Bqg_l, *BWcat_h, *BWcat_l, *BWdo_h, *BWdo_l;
    bf16 *avgh, *avgl, *Xh, *Xl, *Hh, *Hl;
    __half *img16, *pWs16;
    float *pc, *palpha, *pqgp, *pgatesp;
    cudaGetSymbolAddress((void**)&imgh, g_imgh);     cudaGetSymbolAddress((void**)&imgl, g_imgl);
    cudaGetSymbolAddress((void**)&img16, g_img16);   cudaGetSymbolAddress((void**)&pWs16, g_Ws16);
    cudaGetSymbolAddress((void**)&BWatt_h, g_BWatt_h); cudaGetSymbolAddress((void**)&BWatt_l, g_BWatt_l);
    cudaGetSymbolAddress((void**)&BWihc_h, g_BWihc_h); cudaGetSymbolAddress((void**)&BWihc_l, g_BWihc_l);
    cudaGetSymbolAddress((void**)&Bqg_h, g_Bqg_h);   cudaGetSymbolAddress((void**)&Bqg_l, g_Bqg_l);
    cudaGetSymbolAddress((void**)&BWcat_h, g_BWcat_h); cudaGetSymbolAddress((void**)&BWcat_l, g_BWcat_l);
    cudaGetSymbolAddress((void**)&BWdo_h, g_BWdo_h); cudaGetSymbolAddress((void**)&BWdo_l, g_BWdo_l);
    cudaGetSymbolAddress((void**)&avgh, g_avgh);     cudaGetSymbolAddress((void**)&avgl, g_avgl);
    cudaGetSymbolAddress((void**)&Xh, g_Xh);         cudaGetSymbolAddress((void**)&Xl, g_Xl);
    cudaGetSymbolAddress((void**)&Hh, g_Hh);         cudaGetSymbolAddress((void**)&Hl, g_Hl);
    cudaGetSymbolAddress((void**)&pc, g_c);          cudaGetSymbolAddress((void**)&palpha, g_alpha);
    cudaGetSymbolAddress((void**)&pqgp, g_qgp);
    cudaGetSymbolAddress((void**)&pgatesp, g_gatesp);

    cudaFuncSetAttribute(tc_gemm<float>,  cudaFuncAttributeMaxDynamicSharedMemorySize, SMEM_SZ);
    cudaFuncSetAttribute(tc_gemm<__half>, cudaFuncAttributeMaxDynamicSharedMemorySize, SMEM_SZ);

    cudaStream_t s2;
    cudaStreamCreateWithFlags(&s2, cudaStreamNonBlocking);
    cudaEvent_t evFork, evTsplit, evImg, evInit, evDone;
    cudaEvent_t evL[SS], evA[SS];
    cudaEventCreateWithFlags(&evFork, cudaEventDisableTiming);
    cudaEventCreateWithFlags(&evTsplit, cudaEventDisableTiming);
    cudaEventCreateWithFlags(&evImg, cudaEventDisableTiming);
    cudaEventCreateWithFlags(&evInit, cudaEventDisableTiming);
    cudaEventCreateWithFlags(&evDone, cudaEventDisableTiming);
    for (int t = 0; t < SS; t++) {
        cudaEventCreateWithFlags(&evL[t], cudaEventDisableTiming);
        cudaEventCreateWithFlags(&evA[t], cudaEventDisableTiming);
    }

    cudaEventRecord(evFork, 0);
    cudaStreamWaitEvent(s2, evFork, 0);

    // s2: weight transposes. Wcat K order = [emb | h | ctx]
    {
        dim3 blk(32, 8);
        tsplit_kernel<<<dim3(16, 64), blk, 0, s2>>>(W_att, BWatt_h, BWatt_l, EE, HH, EE, 0);
        tsplit_kernel<<<dim3(16, 64), blk, 0, s2>>>(Wih, BWihc_h, BWihc_l, EE, HH, EE, 0);
        tsplit_kernel<<<dim3(16, 64), blk, 0, s2>>>(Wic, BWihc_h + (size_t)HH * EE,
                                                    BWihc_l + (size_t)HH * EE, EE, HH, EE, 0);
        tsplit_kernel<<<dim3(16, 16), blk, 0, s2>>>(U_att, Bqg_h, Bqg_l, HH, HH, HH, 0);
        tsplit_kernel<<<dim3(64, 16), blk, 0, s2>>>(Wfb, Bqg_h + (size_t)HH * HH,
                                                    Bqg_l + (size_t)HH * HH, HH, EE, HH, 0);
        tsplit_kernel<<<dim3(64, 16), blk, 0, s2>>>(Wl, BWcat_h, BWcat_l, HH, G4, XK, XE);
        tsplit_kernel<<<dim3(64, 16), blk, 0, s2>>>(Ul, BWcat_h, BWcat_l, HH, G4, XK, XH);
        tsplit_kernel<<<dim3(64, 64), blk, 0, s2>>>(Wl + (size_t)HH * G4, BWcat_h, BWcat_l,
                                                    EE, G4, XK, XC);
        tsplit_kernel<<<dim3(VPAD / 32, 16), blk, 0, s2>>>(Wdo, BWdo_h, BWdo_l, HH, VV, HH, 0);
        cudaEventRecord(evTsplit, s2);
    }

    imgprep_kernel<<<dim3(EE / 256, BB), 256>>>(img, imgh, imgl, img16, avgh, avgl);
    cudaEventRecord(evImg, 0);

    cudaStreamWaitEvent(s2, evImg, 0);
    tc_gemm<float><<<dim3(HC / 128, 1, 8), 256, SMEM_SZ, s2>>>(
        avgh, avgl, EE, BWihc_h, BWihc_l, EE, nullptr, pgatesp, HC, (long)128 * HC, HC, EE);
    combine_init<<<(BB * HH) / 256, 256, 0, s2>>>(pgatesp, bih, bic, Wemb, cap, pc, Xh, Xl);
    // gatesA(0): K=[emb|h]=1024, z=2 -> slices {4,5}
    tc_gemm<float><<<dim3(16, 1, 2), 256, SMEM_SZ, s2>>>(
        Xh + XE, Xl + XE, XK, BWcat_h + XE, BWcat_l + XE, XK, nullptr,
        pgatesp + (size_t)4 * BB * G4, G4, (long)128 * G4, G4, 1024);
    cudaEventRecord(evA[0], s2);
    cudaEventRecord(evInit, s2);

    cudaStreamWaitEvent(0, evTsplit, 0);
    tc_gemm<__half><<<dim3(4, 196, 1), 256, SMEM_SZ>>>(imgh, imgl, EE, BWatt_h, BWatt_l, EE,
                                                       bW, pWs16, HH, (long)128 * HH, HH, EE);
    cudaStreamWaitEvent(0, evInit, 0);

    for (int t = 0; t < SS; t++) {
        const int zA  = 4 + ((t & 1) << 1);        // this step's gatesA slices
        const int zAn = 4 + (((t + 1) & 1) << 1);  // next step's
        tc_gemm<float><<<dim3(QG / 128, 1, 4), 256, SMEM_SZ>>>(
            Xh + XH, Xl + XH, XK, Bqg_h, Bqg_l, HH, nullptr, pqgp,
            QG, (long)128 * QG, QG, HH);
        attention_kernel<<<BB, 1024>>>(pWs16, pqgp, bU, v_att, bv, palpha,
                                       alphas + (size_t)t * PP);
        ctx_mma_kernel<<<dim3(EE / 512, BB), 256>>>(img16, palpha, pqgp, bfb, Xh, Xl);
        // gatesB: K=ctx (2048), z=4 -> slices 0..3
        tc_gemm<float><<<dim3(16, 1, 4), 256, SMEM_SZ>>>(
            Xh + XC, Xl + XC, XK, BWcat_h + XC, BWcat_l + XC, XK, nullptr,
            pgatesp, G4, (long)128 * G4, G4, 2048);
        cudaStreamWaitEvent(0, evA[t], 0);
        lstm_kernel<<<(BB * HH) / 256, 256>>>(pgatesp, zA, bl, pc, Xh, Xl, Hh, Hl,
                                              Wemb, cap, t);
        cudaEventRecord(evL[t], 0);
        cudaStreamWaitEvent(s2, evL[t], 0);
        if (t + 1 < SS) {
            // gatesA(t+1): overlaps next step's qg/att/ctx on main
            tc_gemm<float><<<dim3(16, 1, 2), 256, SMEM_SZ, s2>>>(
                Xh + XE, Xl + XE, XK, BWcat_h + XE, BWcat_l + XE, XK, nullptr,
                pgatesp + (size_t)zAn * BB * G4, G4, (long)128 * G4, G4, 1024);
            cudaEventRecord(evA[t + 1], s2);
        }
        tc_gemm<float><<<dim3(VPAD / 128, 1, 1), 256, SMEM_SZ, s2>>>(
            Hh + (size_t)t * BB * HH, Hl + (size_t)t * BB * HH, HH,
            BWdo_h, BWdo_l, HH, bdo, preds + (size_t)t * VV, SS * VV, 0L, VV, HH);
    }

    cudaEventRecord(evDone, s2);
    cudaStreamWaitEvent(0, evDone, 0);
}